// round 5
// baseline (speedup 1.0000x reference)
#include <cuda_runtime.h>

// KANLayer_60464549593380 on GB300 (sm_103a):
//   out[b] = sum_d P_d(tanh(x[b,d])), P_d = degree-8 monomial poly from
//   w = hweights @ coeffs (summation reorder + Chebyshev->monomial fold).
// R5: warp-uniform coefficient broadcast (thread = row, warp = 32 rows,
// 4 warp-groups own dim quarters), packed f32x2 Horner, cp.async staging.

#define DEG   8
#define NF    9
#define DDIM  256
#define FDIM  2304
#define F4DIM 576
#define ROWS  64            // rows per block
#define XPITCH 36           // floats per row in stage buffer (9x16B, odd -> conflict-free)

__device__ float g_w[FDIM];

// ---------------- packed f32x2 / MUFU / cp.async helpers ----------------
__device__ __forceinline__ unsigned long long fma2(unsigned long long a,
                                                   unsigned long long b,
                                                   unsigned long long c) {
    unsigned long long d;
    asm("fma.rn.f32x2 %0, %1, %2, %3;" : "=l"(d) : "l"(a), "l"(b), "l"(c));
    return d;
}
__device__ __forceinline__ unsigned long long add2(unsigned long long a,
                                                   unsigned long long b) {
    unsigned long long d;
    asm("add.rn.f32x2 %0, %1, %2;" : "=l"(d) : "l"(a), "l"(b));
    return d;
}
__device__ __forceinline__ unsigned long long pack2(float lo, float hi) {
    unsigned long long d;
    asm("mov.b64 %0, {%1, %2};" : "=l"(d) : "f"(lo), "f"(hi));
    return d;
}
__device__ __forceinline__ float unpack_sum(unsigned long long v) {
    float lo, hi;
    asm("mov.b64 {%0, %1}, %2;" : "=f"(lo), "=f"(hi) : "l"(v));
    return lo + hi;
}
__device__ __forceinline__ float ex2a(float v) {
    float r; asm("ex2.approx.ftz.f32 %0, %1;" : "=f"(r) : "f"(v)); return r;
}
__device__ __forceinline__ float rcpa(float v) {
    float r; asm("rcp.approx.ftz.f32 %0, %1;" : "=f"(r) : "f"(v)); return r;
}
__device__ __forceinline__ float tanh_fast(float v) {
    float e = ex2a(v * -2.885390081777927f);   // exp(-2v); sign-correct for v<0
    return (1.0f - e) * rcpa(1.0f + e);
}
__device__ __forceinline__ void cpa16(void* dst_smem, const void* src) {
    unsigned s = (unsigned)__cvta_generic_to_shared(dst_smem);
    asm volatile("cp.async.cg.shared.global [%0], [%1], 16;" :: "r"(s), "l"(src));
}
__device__ __forceinline__ void cpa_commit() { asm volatile("cp.async.commit_group;"); }
__device__ __forceinline__ void cpa_wait1()  { asm volatile("cp.async.wait_group 1;"); }

// ---------------- Prep: w[f] = sum_n hw[n]*coeffs[n,f] ----------------
__global__ void k_wprep(const float4* __restrict__ c4,
                        const float* __restrict__ hw, int N) {
    __shared__ float4 red[128];
    const int col = blockIdx.x;
    const int t   = threadIdx.x;
    float4 s = make_float4(0.f, 0.f, 0.f, 0.f);
    for (int n = t; n < N; n += 128) {
        float  h = hw[n];
        float4 v = c4[(size_t)n * F4DIM + col];
        s.x = fmaf(h, v.x, s.x);
        s.y = fmaf(h, v.y, s.y);
        s.z = fmaf(h, v.z, s.z);
        s.w = fmaf(h, v.w, s.w);
    }
    red[t] = s;
    __syncthreads();
    #pragma unroll
    for (int o = 64; o >= 1; o >>= 1) {
        if (t < o) {
            float4 b = red[t + o];
            red[t].x += b.x; red[t].y += b.y; red[t].z += b.z; red[t].w += b.w;
        }
        __syncthreads();
    }
    if (t == 0) ((float4*)g_w)[col] = red[0];
}

// Chebyshev -> monomial for one dim's 9 weights.
__device__ __forceinline__ void cheb2mono(const float* __restrict__ w, float* a) {
    a[0] = w[0] - w[2] + w[4] - w[6] + w[8];
    a[1] = w[1] - 3.f * w[3] + 5.f * w[5] - 7.f * w[7];
    a[2] = 2.f * w[2] - 8.f * w[4] + 18.f * w[6] - 32.f * w[8];
    a[3] = 4.f * w[3] - 20.f * w[5] + 56.f * w[7];
    a[4] = 8.f * w[4] - 48.f * w[6] + 160.f * w[8];
    a[5] = 16.f * w[5] - 112.f * w[7];
    a[6] = 32.f * w[6] - 256.f * w[8];
    a[7] = 64.f * w[7];
    a[8] = 128.f * w[8];
}

// ---------------- Main ----------------
// 256 threads = 8 warps. Warp ww: quarter w = ww&3 (dims 64w..64w+63),
// row group rg = ww>>2 (rows 32rg..32rg+31), lane = row within group.
// Chunk c (0..7): warp processes dims [64w+8c, +8) for its 32 rows.
// Coefficient addresses are warp-uniform -> broadcast LDS (1 wavefront).
__global__ void __launch_bounds__(256)
k_main(const float* __restrict__ x, float* __restrict__ out, int B) {
    __shared__ float xs[2][ROWS][XPITCH];            // 18.4 KB
    __shared__ unsigned long long cs[NF][DDIM / 2];  // 9.2 KB
    __shared__ float part[ROWS][4];                  // 1 KB
    const int t    = threadIdx.x;
    const int lane = t & 31;
    const int ww   = t >> 5;
    const int w    = ww & 3;                         // dim quarter
    const int rloc = (ww >> 2) * 32 + lane;          // row within block
    const size_t row0 = (size_t)blockIdx.x * ROWS;
    const float4* xg = (const float4*)x + row0 * 64;

    // Stage chunk 0. Segment s of row r holds dims 64*(s>>1)+8c+4*(s&1) .. +4,
    // stored at xs[buf][r][4s..4s+4). Relative f4 index: r*64 + 16*(s>>1)+(s&1)+2c.
    #pragma unroll
    for (int k = 0; k < 2; ++k) {
        int idx = t + 256 * k;                       // 0..511 (row, seg)
        int r = idx >> 3, s = idx & 7;
        cpa16(&xs[0][r][s * 4], xg + (size_t)r * 64 + 16 * (s >> 1) + (s & 1));
    }
    cpa_commit();

    // Build packed monomial table while chunk 0 is in flight.
    if (t < 128) {
        const int p = t;                             // pair (2p, 2p+1)
        float wl[NF], wh[NF], al[NF], ah[NF];
        #pragma unroll
        for (int k = 0; k < NF; ++k) {
            wl[k] = g_w[(2 * p) * NF + k];
            wh[k] = g_w[(2 * p + 1) * NF + k];
        }
        cheb2mono(wl, al);
        cheb2mono(wh, ah);
        #pragma unroll
        for (int j = 0; j < NF; ++j) cs[j][p] = pack2(al[j], ah[j]);
    }

    unsigned long long accA = pack2(0.f, 0.f);
    unsigned long long accB = pack2(0.f, 0.f);

    #pragma unroll
    for (int c = 0; c < 8; ++c) {
        const int buf = c & 1;
        __syncthreads();                 // buf^1 consumed (c>0); cs ready (c==0)
        if (c < 7) {
            #pragma unroll
            for (int k = 0; k < 2; ++k) {
                int idx = t + 256 * k;
                int r = idx >> 3, s = idx & 7;
                cpa16(&xs[buf ^ 1][r][s * 4],
                      xg + (size_t)r * 64 + 16 * (s >> 1) + (s & 1) + 2 * (c + 1));
            }
        }
        cpa_commit();
        cpa_wait1();                     // chunk c landed (own thread's ops)
        __syncthreads();                 // visible block-wide

        const float* xr = &xs[buf][rloc][8 * w];     // 16B-aligned (144B pitch)
        float4 xa = *(const float4*)xr;
        float4 xb = *(const float4*)(xr + 4);
        float tv[8];
        tv[0] = tanh_fast(xa.x); tv[1] = tanh_fast(xa.y);
        tv[2] = tanh_fast(xa.z); tv[3] = tanh_fast(xa.w);
        tv[4] = tanh_fast(xb.x); tv[5] = tanh_fast(xb.y);
        tv[6] = tanh_fast(xb.z); tv[7] = tanh_fast(xb.w);

        const int P0 = 32 * w + 4 * c;               // warp-uniform
        #pragma unroll
        for (int i = 0; i < 4; ++i) {
            unsigned long long tp = pack2(tv[2 * i], tv[2 * i + 1]);
            unsigned long long h  = cs[DEG][P0 + i];
            #pragma unroll
            for (int j = DEG - 1; j >= 0; --j)
                h = fma2(tp, h, cs[j][P0 + i]);      // broadcast LDS operand
            if (i & 1) accB = add2(accB, h);
            else       accA = add2(accA, h);
        }
    }

    // Combine quarters across the 4 dim-warps via smem.
    part[rloc][w] = unpack_sum(add2(accA, accB));
    __syncthreads();
    if (t < ROWS) {
        float s = part[t][0] + part[t][1] + part[t][2] + part[t][3];
        size_t row = row0 + t;
        if (row < (size_t)B) out[row] = s;
    }
}

extern "C" void kernel_launch(void* const* d_in, const int* in_sizes, int n_in,
                              void* d_out, int out_size) {
    const float* x      = (const float*)d_in[0];
    const float* coeffs = (const float*)d_in[1];
    const float* hw     = (const float*)d_in[2];
    float* out = (float*)d_out;

    const int B = out_size;       // 32768 = 512 * 64
    const int N = in_sizes[2];    // 256

    k_wprep<<<F4DIM, 128>>>((const float4*)coeffs, hw, N);
    k_main<<<(B + ROWS - 1) / ROWS, 256>>>(x, out, B);
}